// round 1
// baseline (speedup 1.0000x reference)
#include <cuda_runtime.h>

// TNorm: out[b, ((i0*8+i1)*8+i2)*8+i3] = g[b,0,i0]*g[b,1,i1]*g[b,2,i2]*g[b,3,i3]
// x: (16384, 32) fp32, out: (16384, 4096) fp32.
// Pure HBM-write-bound: 256 MiB stores, 2 MiB loads.

#define BATCH 16384

__global__ __launch_bounds__(128, 16)
void tnorm_kernel(const float* __restrict__ x, float* __restrict__ out) {
    __shared__ float g[32];

    const int b = blockIdx.x;
    const int t = threadIdx.x;

    // 8 threads load the whole 32-float row as float4s
    if (t < 8) {
        reinterpret_cast<float4*>(g)[t] =
            reinterpret_cast<const float4*>(x + (size_t)b * 32)[t];
    }
    __syncthreads();

    const float* g0 = g;
    const float* g1 = g + 8;
    const float* g2 = g + 16;
    const float* g3 = g + 24;

    // Thread t owns outputs [t*32, t*32+32): fixed i0,i1; i2 spans 4; i3 spans 8.
    const int i0  = t >> 4;          // t / 16
    const int i1  = (t >> 1) & 7;    // (t % 16) / 2
    const int i2b = (t & 1) * 4;

    const float p01 = g0[i0] * g1[i1];

    // g3 as two float4s (broadcast from smem)
    const float4 a = *reinterpret_cast<const float4*>(g3);
    const float4 c = *reinterpret_cast<const float4*>(g3 + 4);

    float4* o = reinterpret_cast<float4*>(out + (size_t)b * 4096 + t * 32);

    #pragma unroll
    for (int k = 0; k < 4; k++) {
        const float p = p01 * g2[i2b + k];
        float4 v0 = make_float4(p * a.x, p * a.y, p * a.z, p * a.w);
        float4 v1 = make_float4(p * c.x, p * c.y, p * c.z, p * c.w);
        // Streaming stores: output is write-once, never re-read.
        __stcs(o + k * 2,     v0);
        __stcs(o + k * 2 + 1, v1);
    }
}

extern "C" void kernel_launch(void* const* d_in, const int* in_sizes, int n_in,
                              void* d_out, int out_size) {
    const float* x = (const float*)d_in[0];
    float* out = (float*)d_out;
    tnorm_kernel<<<BATCH, 128>>>(x, out);
}

// round 2
// speedup vs baseline: 2.0809x; 2.0809x over previous
#include <cuda_runtime.h>
#include <cstdint>

// TNorm: out[b, ((i0*8+i1)*8+i2)*8+i3] = g[b,0,i0]*g[b,1,i1]*g[b,2,i2]*g[b,3,i3]
// x: (16384, 32) fp32 -> out: (16384, 4096) fp32.  256 MiB pure write stream.
//
// R1 finding: LSU store path limited us to 2.3 TB/s (issue=3.7%, L2=60%, DRAM=28%).
// R2: compute each 16KB row in SMEM, drain via TMA bulk store (cp.async.bulk S->G),
// double-buffered, persistent CTAs. TMA gives deep chip-wide in-flight store bytes.

#define BATCH       16384
#define ROW_FLOATS  4096
#define ROW_BYTES   (ROW_FLOATS * 4)
#define NTHREADS    128
#define GRID_CTAS   (148 * 7)

__device__ __forceinline__ uint32_t smem_u32(const void* p) {
    return (uint32_t)__cvta_generic_to_shared(p);
}

__global__ __launch_bounds__(NTHREADS)
void tnorm_tma_kernel(const float* __restrict__ x, float* __restrict__ out) {
    __shared__ float buf[2][ROW_FLOATS];   // 32 KB double buffer
    __shared__ float g[32];

    const int t = threadIdx.x;

    // Per-thread invariant index decomposition (see header):
    // chunk k (=i0) 0..7, thread t writes float4 at k*512 + t*4.
    // i1 = t>>4, i2 = (t>>1)&7, i3base = (t&1)*4.
    const int i1 = t >> 4;
    const int i2 = (t >> 1) & 7;
    const int i3b = (t & 1) * 4;

    int it = 0;
    for (int row = blockIdx.x; row < BATCH; row += gridDim.x, ++it) {
        const int bsel = it & 1;
        float* b = buf[bsel];

        // Ensure the bulk store issued 2 iterations ago (same buffer) has
        // finished READING smem before we overwrite it. <=1 group pending.
        if (t == 0)
            asm volatile("cp.async.bulk.wait_group.read 1;" ::: "memory");

        // Stage this row's 32 inputs.
        if (t < 8)
            reinterpret_cast<float4*>(g)[t] =
                reinterpret_cast<const float4*>(x + (size_t)row * 32)[t];
        __syncthreads();   // covers wait_group + g staging

        const float p12 = g[8 + i1] * g[16 + i2];
        const float4 a3 = *reinterpret_cast<const float4*>(&g[24 + i3b]);

        #pragma unroll
        for (int k = 0; k < 8; k++) {
            const float s = g[k] * p12;   // g0[k] * g1[i1] * g2[i2]
            float4 v = make_float4(s * a3.x, s * a3.y, s * a3.z, s * a3.w);
            // conflict-free: lanes write consecutive 16B
            *reinterpret_cast<float4*>(b + k * 512 + t * 4) = v;
        }
        __syncthreads();

        if (t == 0) {
            // Order all threads' generic-proxy STS before async-proxy TMA read.
            asm volatile("fence.proxy.async.shared::cta;" ::: "memory");
            const uint32_t saddr = smem_u32(b);
            float* dst = out + (size_t)row * ROW_FLOATS;
            asm volatile(
                "cp.async.bulk.global.shared::cta.bulk_group [%0], [%1], %2;"
                :: "l"(dst), "r"(saddr), "n"(ROW_BYTES) : "memory");
            asm volatile("cp.async.bulk.commit_group;" ::: "memory");
        }
        // No barrier needed here: next iteration's first barrier orders everyone.
    }

    // SMEM is deallocated at CTA exit; drain all pending bulk reads first.
    if (t == 0)
        asm volatile("cp.async.bulk.wait_group.read 0;" ::: "memory");
    __syncthreads();
}

extern "C" void kernel_launch(void* const* d_in, const int* in_sizes, int n_in,
                              void* d_out, int out_size) {
    const float* x = (const float*)d_in[0];
    float* out = (float*)d_out;
    tnorm_tma_kernel<<<GRID_CTAS, NTHREADS>>>(x, out);
}

// round 3
// speedup vs baseline: 2.5442x; 1.2226x over previous
#include <cuda_runtime.h>
#include <cstdint>

// TNorm: out[b, ((i0*8+i1)*8+i2)*8+i3] = prod of g[b,i,:] factors.
// x: (16384,32) fp32 -> out: (16384,4096) fp32. 256 MiB pure write stream.
//
// R2: TMA bulk store path -> 55.4us (DRAM 51%, all pipes ~50%, CTAs parked in
// wait_group). R3: evict_first L2 policy on the output stream + triple
// buffering (2 groups in flight/CTA) + x-row prefetch.

#define BATCH       16384
#define ROW_FLOATS  4096
#define ROW_BYTES   (ROW_FLOATS * 4)
#define NT          128
#define NBUF        3
#define GRID_CTAS   (148 * 4)
#define SMEM_BYTES  (NBUF * ROW_BYTES + 2 * 32 * 4)

__global__ __launch_bounds__(NT)
void tnorm_tma3_kernel(const float* __restrict__ x, float* __restrict__ out) {
    extern __shared__ float smem[];
    float* buf = smem;                       // NBUF x 4096 floats
    float* g   = smem + NBUF * ROW_FLOATS;   // 2 x 32 floats (x-row double buffer)

    const int t = threadIdx.x;
    const int i1  = t >> 4;
    const int i2  = (t >> 1) & 7;
    const int i3b = (t & 1) * 4;

    // Streaming L2 policy: output lines are write-once, evict first.
    uint64_t pol;
    asm volatile("createpolicy.fractional.L2::evict_first.b64 %0, 1.0;" : "=l"(pol));

    // Prologue: stage g for the first row.
    const int row0 = blockIdx.x;
    if (t < 8 && row0 < BATCH)
        reinterpret_cast<float4*>(g)[t] =
            reinterpret_cast<const float4*>(x + (size_t)row0 * 32)[t];
    __syncthreads();

    int it = 0;
    for (int row = row0; row < BATCH; row += gridDim.x, ++it) {
        float* b = buf + (it % NBUF) * ROW_FLOATS;
        const float* gc = g + (it & 1) * 32;

        // Guard current buffer: group (it-NBUF) must have finished reading smem.
        if (t == 0)
            asm volatile("cp.async.bulk.wait_group.read 2;" ::: "memory");

        // Prefetch next row's 32 inputs (hidden behind this iteration).
        const int nrow = row + gridDim.x;
        if (t < 8 && nrow < BATCH)
            reinterpret_cast<float4*>(g + ((it + 1) & 1) * 32)[t] =
                reinterpret_cast<const float4*>(x + (size_t)nrow * 32)[t];

        __syncthreads();   // wait_group visible to all; gc stable

        const float p12 = gc[8 + i1] * gc[16 + i2];
        const float4 a3 = *reinterpret_cast<const float4*>(&gc[24 + i3b]);

        #pragma unroll
        for (int k = 0; k < 8; k++) {
            const float s = gc[k] * p12;         // g0[k]*g1[i1]*g2[i2]
            float4 v = make_float4(s * a3.x, s * a3.y, s * a3.z, s * a3.w);
            *reinterpret_cast<float4*>(b + k * 512 + t * 4) = v;  // conflict-free
        }
        __syncthreads();

        if (t == 0) {
            asm volatile("fence.proxy.async.shared::cta;" ::: "memory");
            const uint32_t saddr = (uint32_t)__cvta_generic_to_shared(b);
            float* dst = out + (size_t)row * ROW_FLOATS;
            asm volatile(
                "cp.async.bulk.global.shared::cta.bulk_group.L2::cache_hint "
                "[%0], [%1], %2, %3;"
                :: "l"(dst), "r"(saddr), "n"(ROW_BYTES), "l"(pol) : "memory");
            asm volatile("cp.async.bulk.commit_group;" ::: "memory");
        }
    }

    // Drain all pending bulk reads before SMEM is deallocated at CTA exit.
    if (t == 0)
        asm volatile("cp.async.bulk.wait_group.read 0;" ::: "memory");
    __syncthreads();
}

extern "C" void kernel_launch(void* const* d_in, const int* in_sizes, int n_in,
                              void* d_out, int out_size) {
    const float* x = (const float*)d_in[0];
    float* out = (float*)d_out;
    static bool attr_set = false;
    if (!attr_set) {
        cudaFuncSetAttribute(tnorm_tma3_kernel,
                             cudaFuncAttributeMaxDynamicSharedMemorySize,
                             SMEM_BYTES);
        attr_set = true;
    }
    tnorm_tma3_kernel<<<GRID_CTAS, NT, SMEM_BYTES>>>(x, out);
}